// round 15
// baseline (speedup 1.0000x reference)
#include <cuda_runtime.h>
#include <cuda_fp16.h>
#include <math.h>

typedef unsigned int u32;

#define D_ 1024
#define S_ 2048
#define SCALE_ 0.125f
#define LOG2E_ 1.4426950408889634f

// ---------------- device-global scratch ------------------------------------
__device__ __half g_xh   [(size_t)8192 * 1024];
__device__ __half g_wqh  [(size_t)3072 * 1024];   // w_qkv^T fp16 (q rows pre-scaled by SCALE*LOG2E)
__device__ __half g_qh   [(size_t)64 * S_ * 64];  // [bh][s][dh] (scaled, log2 domain)
__device__ __half g_kh   [(size_t)64 * S_ * 64];
__device__ __half g_vTh  [(size_t)64 * 64 * S_];  // [bh][dh][s]
__device__ __half g_aoh  [(size_t)8192 * D_];
__device__ __half g_woutTh[(size_t)D_ * D_];

// ---------------- helpers ---------------------------------------------------
__device__ __forceinline__ u32 smem_u32(const void* p) {
    u32 a;
    asm("{ .reg .u64 t; cvta.to.shared.u64 t, %1; cvt.u32.u64 %0, t; }" : "=r"(a) : "l"(p));
    return a;
}
#define CP16(s, g) asm volatile("cp.async.cg.shared.global [%0], [%1], 16;" :: "r"(s), "l"(g))
#define CPC        asm volatile("cp.async.commit_group;")
#define CPW(n)     asm volatile("cp.async.wait_group %0;" :: "n"(n))

#define LDSM4(r0, r1, r2, r3, addr) asm volatile( \
    "ldmatrix.sync.aligned.m8n8.x4.shared.b16 {%0,%1,%2,%3}, [%4];" \
    : "=r"(r0), "=r"(r1), "=r"(r2), "=r"(r3) : "r"(addr))

#define MMA_F16(c, a0,a1,a2,a3, b0,b1) asm volatile( \
    "mma.sync.aligned.m16n8k16.row.col.f32.f16.f16.f32 " \
    "{%0,%1,%2,%3},{%4,%5,%6,%7},{%8,%9},{%0,%1,%2,%3};" \
    : "+f"((c)[0]), "+f"((c)[1]), "+f"((c)[2]), "+f"((c)[3]) \
    : "r"(a0), "r"(a1), "r"(a2), "r"(a3), "r"(b0), "r"(b1))

// pack two floats -> half2 ({lo=x0, hi=x1}) then 2^x elementwise
#define EXP2_PACK(dst, x0, x1) do { \
    u32 _p; \
    asm("cvt.rn.f16x2.f32 %0, %1, %2;" : "=r"(_p) : "f"(x1), "f"(x0)); \
    asm("ex2.approx.f16x2 %0, %0;" : "+r"(_p)); \
    (dst) = _p; \
} while (0)

#define ZERO_CB(c) { _Pragma("unroll") for (int m = 0; m < 4; ++m) \
    _Pragma("unroll") for (int n = 0; n < 8; ++n) \
    _Pragma("unroll") for (int r = 0; r < 4; ++r) (c)[m][n][r] = 0.f; }

#define ZERO_C2(c, NT) { _Pragma("unroll") for (int n = 0; n < NT; ++n) \
    _Pragma("unroll") for (int r = 0; r < 4; ++r) (c)[n][r] = 0.f; }

// ============================================================================
// fp16 GEMM mainloop, BIG tile: C[256x128] = A[256x1024] @ B[128x1024]^T.
// 8 warps 4x2, warp tile 64x64 -> LDSM:MMA = 1:4 (crossbar relief).
// k=64 stages (A 32KB + B 16KB), 3-stage cp.async, 1 CTA/SM.
// ============================================================================
#define GSTG2 49152
__device__ __forceinline__ void gemm16_big(
    const __half* __restrict__ A, const __half* __restrict__ Bm,
    char* dsm, u32 sb, float (&c)[4][8][4])
{
    const int tid = threadIdx.x, lane = tid & 31, wid = tid >> 5;
    const int wm = wid >> 1, wn = wid & 1;
    const int li = lane & 7, mi = lane >> 3;

    u32 sA[8]; const __half* gA[8];
    #pragma unroll
    for (int p = 0; p < 8; ++p) {
        int id = tid + p * 256;
        int row = id >> 3, cc = id & 7;
        u32 sw = (u32)(row * 128 + ((cc ^ (row & 7)) << 4));
        sA[p] = sb + sw;
        gA[p] = A + (size_t)row * 1024 + cc * 8;
    }
    u32 sB[4]; const __half* gB[4];
    #pragma unroll
    for (int p = 0; p < 4; ++p) {
        int id = tid + p * 256;
        int row = id >> 3, cc = id & 7;
        u32 sw = (u32)(row * 128 + ((cc ^ (row & 7)) << 4));
        sB[p] = sb + 32768 + sw;
        gB[p] = Bm + (size_t)row * 1024 + cc * 8;
    }
    auto load = [&](int s) {
        u32 off = (u32)((s % 3) * GSTG2);
        int k0 = s << 6;
        #pragma unroll
        for (int p = 0; p < 8; ++p) CP16(sA[p] + off, gA[p] + k0);
        #pragma unroll
        for (int p = 0; p < 4; ++p) CP16(sB[p] + off, gB[p] + k0);
        CPC;
    };
    load(0); load(1);

    const u32 bfrag = (u32)(32768 + wn * 8192 + li * 128 + ((mi ^ li) << 4));
    const u32 aRow0 = (u32)((wm * 64 + ((mi & 1) << 3) + li) * 128);

    for (int ch = 0; ch < 16; ++ch) {
        CPW(1);
        __syncthreads();
        if (ch + 2 < 16) load(ch + 2); else CPC;
        u32 st = sb + (u32)((ch % 3) * GSTG2);

        #pragma unroll
        for (int half = 0; half < 2; ++half) {
            u32 hx = (u32)(half << 6);
            // B fragments: 8 n-tiles x k32
            u32 bb[8][4];
            #pragma unroll
            for (int nt = 0; nt < 8; ++nt)
                LDSM4(bb[nt][0], bb[nt][1], bb[nt][2], bb[nt][3],
                      (st + bfrag + nt * 1024) ^ hx);
            const int kt0 = half * 2, kt1 = half * 2 + 1;
            const u32 x0 = (u32)(((((kt0 << 1) | (mi >> 1))) ^ li) << 4);
            const u32 x1 = (u32)(((((kt1 << 1) | (mi >> 1))) ^ li) << 4);

            #pragma unroll
            for (int mt = 0; mt < 4; ++mt) {
                u32 aadr = st + aRow0 + mt * 2048;
                u32 a0[4], a1[4];
                LDSM4(a0[0], a0[1], a0[2], a0[3], aadr + x0);
                LDSM4(a1[0], a1[1], a1[2], a1[3], aadr + x1);
                #pragma unroll
                for (int nt = 0; nt < 8; ++nt)
                    MMA_F16(c[mt][nt], a0[0], a0[1], a0[2], a0[3],
                            bb[nt][0], bb[nt][1]);
                #pragma unroll
                for (int nt = 0; nt < 8; ++nt)
                    MMA_F16(c[mt][nt], a1[0], a1[1], a1[2], a1[3],
                            bb[nt][2], bb[nt][3]);
            }
        }
    }
}

// ============================================================================
// Prep kernels
// ============================================================================
__global__ __launch_bounds__(256) void k_xh(const float* __restrict__ x)
{
    size_t base = ((size_t)blockIdx.x * 256 + threadIdx.x) * 8;
    float4 v0 = *(const float4*)(x + base);
    float4 v1 = *(const float4*)(x + base + 4);
    __half2 h0 = __floats2half2_rn(v0.x, v0.y);
    __half2 h1 = __floats2half2_rn(v0.z, v0.w);
    __half2 h2 = __floats2half2_rn(v1.x, v1.y);
    __half2 h3 = __floats2half2_rn(v1.z, v1.w);
    *(uint4*)(g_xh + base) = make_uint4(*(u32*)&h0, *(u32*)&h1, *(u32*)&h2, *(u32*)&h3);
}

__global__ __launch_bounds__(256) void k_wqh(const float* __restrict__ w)
{
    __shared__ float tile[32][33];
    int bx = blockIdx.x * 32, by = blockIdx.y * 32;
    int tx = threadIdx.x, ty = threadIdx.y;
    float sc = (bx < 1024) ? SCALE_ * LOG2E_ : 1.0f;
    #pragma unroll
    for (int i = 0; i < 32; i += 8)
        tile[ty + i][tx] = w[(size_t)(by + ty + i) * 3072 + bx + tx];
    __syncthreads();
    #pragma unroll
    for (int i = 0; i < 32; i += 8)
        g_wqh[(size_t)(bx + ty + i) * 1024 + by + tx] = __float2half(tile[tx][ty + i] * sc);
}

__global__ __launch_bounds__(256) void k_woutT(const float* __restrict__ w)
{
    __shared__ float tile[32][33];
    int bx = blockIdx.x * 32, by = blockIdx.y * 32;
    int tx = threadIdx.x, ty = threadIdx.y;
    #pragma unroll
    for (int i = 0; i < 32; i += 8)
        tile[ty + i][tx] = w[(size_t)(by + ty + i) * D_ + bx + tx];
    __syncthreads();
    #pragma unroll
    for (int i = 0; i < 32; i += 8)
        g_woutTh[(size_t)(bx + ty + i) * D_ + by + tx] = __float2half(tile[tx][ty + i]);
}

// ============================================================================
// Kernel 1: QKV projection (fp16 1x, 256x128 tile). q/k -> [bh][s][dh];
// V written transposed directly into g_vTh.
// ============================================================================
__global__ __launch_bounds__(256, 1) void k_qkv(const float* __restrict__ bias)
{
    extern __shared__ __align__(16) char dsm[];
    u32 sb = smem_u32(dsm);
    const int row0 = blockIdx.y * 256, col0 = blockIdx.x * 128;

    float c[4][8][4]; ZERO_CB(c);
    gemm16_big(g_xh + (size_t)row0 * 1024, g_wqh + (size_t)col0 * 1024, dsm, sb, c);

    const int lane = threadIdx.x & 31, wid = threadIdx.x >> 5;
    const int wm = wid >> 1, wn = wid & 1, g = lane >> 2, t = lane & 3;
    const int three = col0 >> 10;
    const float bsc = (three == 0) ? SCALE_ * LOG2E_ : 1.0f;
    #pragma unroll
    for (int nt = 0; nt < 8; ++nt) {
        int gcol = col0 + wn * 64 + nt * 8 + t * 2;
        float b0 = __ldg(bias + gcol) * bsc, b1 = __ldg(bias + gcol + 1) * bsc;
        int h = (gcol >> 6) & 15, dh = gcol & 63;
        #pragma unroll
        for (int mt = 0; mt < 4; ++mt)
            #pragma unroll
            for (int hh = 0; hh < 2; ++hh) {
                int gm = row0 + wm * 64 + mt * 16 + hh * 8 + g;
                int b = gm >> 11, s = gm & 2047;
                float v0 = c[mt][nt][hh * 2] + b0, v1 = c[mt][nt][hh * 2 + 1] + b1;
                if (three == 2) {
                    size_t vb = ((size_t)(b * 16 + h) * 64 + dh) * S_ + s;
                    g_vTh[vb]      = __float2half(v0);
                    g_vTh[vb + S_] = __float2half(v1);
                } else {
                    __half* dst = (three == 0) ? g_qh : g_kh;
                    size_t base = ((size_t)(b * 16 + h) * S_ + s) * 64 + dh;
                    __half2 hv = __floats2half2_rn(v0, v1);
                    *(u32*)(dst + base) = *(u32*)&hv;
                }
            }
    }
}

// ============================================================================
// Kernel 2: fused flash attention (round-14 champion structure, unchanged).
// ============================================================================
#define ATQ   16384
#define ATSTG 16384
__global__ __launch_bounds__(256, 2) void k_attn()
{
    extern __shared__ __align__(16) char dsm[];
    u32 sb = smem_u32(dsm);
    const int tid = threadIdx.x, lane = tid & 31, wid = tid >> 5;
    const int g = lane >> 2, t = lane & 3;
    const int li = lane & 7, mi = lane >> 3;
    const int bh = blockIdx.y, row0 = blockIdx.x * 128;

    // Q producer (group 0)
    {
        const __half* qg = g_qh + ((size_t)bh * S_ + row0) * 64;
        #pragma unroll
        for (int p = 0; p < 4; ++p) {
            int id = tid + p * 256;
            int row = id >> 3, cc = id & 7;
            u32 off = (u32)(row * 128 + ((cc ^ (row & 7)) << 4));
            CP16(sb + off, qg + (size_t)row * 64 + cc * 8);
        }
        CPC;
    }

    // KV producers
    u32 kOff[2], vOff[2];
    const __half* kG[2];
    const __half* vG[2];
    #pragma unroll
    for (int p = 0; p < 2; ++p) {
        int id = tid + p * 256;
        int row = id >> 3, cc = id & 7;
        u32 sw = (u32)(row * 128 + ((cc ^ (row & 7)) << 4));
        kOff[p] = sw;
        kG[p] = g_kh + ((size_t)bh * S_ + row) * 64 + cc * 8;
        vOff[p] = 8192 + sw;
        vG[p] = g_vTh + ((size_t)bh * 64 + row) * S_ + cc * 8;
    }
    auto loadKV = [&](int it) {
        u32 so = sb + ATQ + (u32)((it & 3) * ATSTG);
        int kv0 = it * 64;
        #pragma unroll
        for (int p = 0; p < 2; ++p) CP16(so + kOff[p], kG[p] + (size_t)kv0 * 64);
        #pragma unroll
        for (int p = 0; p < 2; ++p) CP16(so + vOff[p], vG[p] + kv0);
        CPC;
    };
    loadKV(0); loadKV(1); loadKV(2);

    // Q fragments -> registers
    CPW(3);
    __syncthreads();
    u32 qf[4][4];
    {
        u32 qBase = sb + (u32)((wid * 16 + ((mi & 1) << 3) + li) * 128);
        #pragma unroll
        for (int kt = 0; kt < 4; ++kt) {
            u32 x = (u32)(((((kt << 1) | (mi >> 1))) ^ li) << 4);
            LDSM4(qf[kt][0], qf[kt][1], qf[kt][2], qf[kt][3], qBase + x);
        }
    }

    const u32 fragBase = (u32)(li * 128 + ((mi ^ li) << 4));
    const u32 ONE2 = 0x3C003C00u;   // half2(1, 1)

    float co[8][4]; ZERO_C2(co, 8);
    float cls[4];
    #pragma unroll
    for (int r = 0; r < 4; ++r) cls[r] = 0.f;

    for (int it = 0; it < 32; ++it) {
        CPW(2);
        __syncthreads();
        if (it + 3 < 32) loadKV(it + 3); else CPC;
        u32 stK = sb + ATQ + (u32)((it & 3) * ATSTG);
        u32 stV = stK + 8192;

        // S(log2) = Q K^T
        float cs[8][4]; ZERO_C2(cs, 8);
        #pragma unroll
        for (int nt = 0; nt < 8; ++nt) {
            u32 k0, k1, k2, k3, k4, k5, k6, k7;
            u32 adr = stK + fragBase + nt * 1024;
            LDSM4(k0, k1, k2, k3, adr);
            LDSM4(k4, k5, k6, k7, adr ^ 64);
            MMA_F16(cs[nt], qf[0][0], qf[0][1], qf[0][2], qf[0][3], k0, k1);
            MMA_F16(cs[nt], qf[1][0], qf[1][1], qf[1][2], qf[1][3], k2, k3);
            MMA_F16(cs[nt], qf[2][0], qf[2][1], qf[2][2], qf[2][3], k4, k5);
            MMA_F16(cs[nt], qf[3][0], qf[3][1], qf[3][2], qf[3][3], k6, k7);
        }

        // P = 2^S in fp16x2; pack into PV A-fragments
        u32 ap[4][4];
        #pragma unroll
        for (int nt = 0; nt < 8; ++nt) {
            u32 p01, p23;
            EXP2_PACK(p01, cs[nt][0], cs[nt][1]);
            EXP2_PACK(p23, cs[nt][2], cs[nt][3]);
            ap[nt >> 1][(nt & 1) * 2 + 0] = p01;
            ap[nt >> 1][(nt & 1) * 2 + 1] = p23;
        }

        // row sums (exact fp32)
        #pragma unroll
        for (int kt = 0; kt < 4; ++kt)
            MMA_F16(cls, ap[kt][0], ap[kt][1], ap[kt][2], ap[kt][3], ONE2, ONE2);

        // O += P V
        #pragma unroll
        for (int nt = 0; nt < 8; ++nt) {
            u32 v0, v1, v2, v3, v4, v5, v6, v7;
            u32 adr = stV + fragBase + nt * 1024;
            LDSM4(v0, v1, v2, v3, adr);
            LDSM4(v4, v5, v6, v7, adr ^ 64);
            MMA_F16(co[nt], ap[0][0], ap[0][1], ap[0][2], ap[0][3], v0, v1);
            MMA_F16(co[nt], ap[1][0], ap[1][1], ap[1][2], ap[1][3], v2, v3);
            MMA_F16(co[nt], ap[2][0], ap[2][1], ap[2][2], ap[2][3], v4, v5);
            MMA_F16(co[nt], ap[3][0], ap[3][1], ap[3][2], ap[3][3], v6, v7);
        }
    }

    // normalize and write (cls[0]/cls[2] hold this thread's row sums)
    float inv0 = 1.0f / cls[0], inv1 = 1.0f / cls[2];

    const int b = bh >> 4, h = bh & 15;
    int r0 = row0 + wid * 16 + g;
    __half* o0 = g_aoh + ((size_t)b * S_ + r0) * D_ + h * 64;
    __half* o1 = o0 + (size_t)8 * D_;
    #pragma unroll
    for (int nt = 0; nt < 8; ++nt) {
        int dh = nt * 8 + t * 2;
        __half2 w0 = __floats2half2_rn(co[nt][0] * inv0, co[nt][1] * inv0);
        __half2 w1 = __floats2half2_rn(co[nt][2] * inv1, co[nt][3] * inv1);
        *(u32*)(o0 + dh) = *(u32*)&w0;
        *(u32*)(o1 + dh) = *(u32*)&w1;
    }
}

// ============================================================================
// Kernel 3: output projection (fp16 1x, 256x128 tile)
// ============================================================================
__global__ __launch_bounds__(256, 1) void k_out(
    const float* __restrict__ bias, float* __restrict__ out)
{
    extern __shared__ __align__(16) char dsm[];
    u32 sb = smem_u32(dsm);
    const int row0 = blockIdx.y * 256, col0 = blockIdx.x * 128;

    float c[4][8][4]; ZERO_CB(c);
    gemm16_big(g_aoh + (size_t)row0 * D_, g_woutTh + (size_t)col0 * D_, dsm, sb, c);

    const int lane = threadIdx.x & 31, wid = threadIdx.x >> 5;
    const int wm = wid >> 1, wn = wid & 1, g = lane >> 2, t = lane & 3;
    #pragma unroll
    for (int nt = 0; nt < 8; ++nt) {
        int gcol = col0 + wn * 64 + nt * 8 + t * 2;
        float b0 = __ldg(bias + gcol), b1 = __ldg(bias + gcol + 1);
        #pragma unroll
        for (int mt = 0; mt < 4; ++mt)
            #pragma unroll
            for (int hh = 0; hh < 2; ++hh) {
                int gm = row0 + wm * 64 + mt * 16 + hh * 8 + g;
                *(float2*)(out + (size_t)gm * D_ + gcol) =
                    make_float2(c[mt][nt][hh * 2] + b0, c[mt][nt][hh * 2 + 1] + b1);
            }
    }
}

// ---------------------------------------------------------------------------
#define DYN_BIG (3 * GSTG2)         // 147456
#define DYN_ATT (ATQ + 4 * ATSTG)   // 81920

extern "C" void kernel_launch(void* const* d_in, const int* in_sizes, int n_in,
                              void* d_out, int out_size)
{
    (void)in_sizes; (void)n_in; (void)out_size;
    const float* x     = (const float*)d_in[0];
    const float* w_qkv = (const float*)d_in[1];
    const float* b_qkv = (const float*)d_in[2];
    const float* w_out = (const float*)d_in[3];
    const float* b_out = (const float*)d_in[4];
    float* out = (float*)d_out;

    cudaFuncSetAttribute(k_qkv,  cudaFuncAttributeMaxDynamicSharedMemorySize, DYN_BIG);
    cudaFuncSetAttribute(k_attn, cudaFuncAttributeMaxDynamicSharedMemorySize, DYN_ATT);
    cudaFuncSetAttribute(k_out,  cudaFuncAttributeMaxDynamicSharedMemorySize, DYN_BIG);

    k_xh<<<4096, 256>>>(x);
    k_wqh<<<dim3(96, 32), dim3(32, 8)>>>(w_qkv);
    k_woutT<<<dim3(32, 32), dim3(32, 8)>>>(w_out);

    k_qkv<<<dim3(24, 32), 256, DYN_BIG>>>(b_qkv);
    k_attn<<<dim3(16, 64), 256, DYN_ATT>>>();
    k_out<<<dim3(8, 32), 256, DYN_BIG>>>(b_out, out);
}

// round 16
// speedup vs baseline: 1.1087x; 1.1087x over previous
#include <cuda_runtime.h>
#include <cuda_fp16.h>
#include <math.h>

typedef unsigned int u32;

#define D_ 1024
#define S_ 2048
#define SCALE_ 0.125f
#define LOG2E_ 1.4426950408889634f

// ---------------- device-global scratch ------------------------------------
__device__ __half g_xh   [(size_t)8192 * 1024];
__device__ __half g_wqh  [(size_t)3072 * 1024];   // w_qkv^T fp16 (q rows pre-scaled by SCALE*LOG2E)
__device__ __half g_qh   [(size_t)64 * S_ * 64];  // [bh][s][dh] (scaled, log2 domain)
__device__ __half g_kh   [(size_t)64 * S_ * 64];
__device__ __half g_vTh  [(size_t)64 * 64 * S_];  // [bh][dh][s]
__device__ __half g_aoh  [(size_t)8192 * D_];
__device__ __half g_woutTh[(size_t)D_ * D_];

// ---------------- helpers ---------------------------------------------------
__device__ __forceinline__ u32 smem_u32(const void* p) {
    u32 a;
    asm("{ .reg .u64 t; cvta.to.shared.u64 t, %1; cvt.u32.u64 %0, t; }" : "=r"(a) : "l"(p));
    return a;
}
#define CP16(s, g) asm volatile("cp.async.cg.shared.global [%0], [%1], 16;" :: "r"(s), "l"(g))
#define CPC        asm volatile("cp.async.commit_group;")
#define CPW(n)     asm volatile("cp.async.wait_group %0;" :: "n"(n))

#define LDSM4(r0, r1, r2, r3, addr) asm volatile( \
    "ldmatrix.sync.aligned.m8n8.x4.shared.b16 {%0,%1,%2,%3}, [%4];" \
    : "=r"(r0), "=r"(r1), "=r"(r2), "=r"(r3) : "r"(addr))

#define MMA_F16(c, a0,a1,a2,a3, b0,b1) asm volatile( \
    "mma.sync.aligned.m16n8k16.row.col.f32.f16.f16.f32 " \
    "{%0,%1,%2,%3},{%4,%5,%6,%7},{%8,%9},{%0,%1,%2,%3};" \
    : "+f"((c)[0]), "+f"((c)[1]), "+f"((c)[2]), "+f"((c)[3]) \
    : "r"(a0), "r"(a1), "r"(a2), "r"(a3), "r"(b0), "r"(b1))

// pack two floats -> half2 ({lo=x0, hi=x1}) then 2^x elementwise
#define EXP2_PACK(dst, x0, x1) do { \
    u32 _p; \
    asm("cvt.rn.f16x2.f32 %0, %1, %2;" : "=r"(_p) : "f"(x1), "f"(x0)); \
    asm("ex2.approx.f16x2 %0, %0;" : "+r"(_p)); \
    (dst) = _p; \
} while (0)

#define ZERO_C3(c, MT) { _Pragma("unroll") for (int m = 0; m < MT; ++m) \
    _Pragma("unroll") for (int n = 0; n < 4; ++n) \
    _Pragma("unroll") for (int r = 0; r < 4; ++r) (c)[m][n][r] = 0.f; }

#define ZERO_C2(c, NT) { _Pragma("unroll") for (int n = 0; n < NT; ++n) \
    _Pragma("unroll") for (int r = 0; r < 4; ++r) (c)[n][r] = 0.f; }

// ============================================================================
// fp16 GEMM mainloop (round-14 champion, unchanged): C[128x128] = A @ B^T.
// k=64 stages, 128B rows, swizzle chunk ^= row&7, 3-stage cp.async,
// distance-1 A prefetch, producer issue split across the two k=32 halves.
// ============================================================================
#define GSTG 32768
__device__ __forceinline__ void gemm16_1024(
    const __half* __restrict__ A, const __half* __restrict__ Bm,
    char* dsm, u32 sb, float (&c)[4][4][4])
{
    const int tid = threadIdx.x, lane = tid & 31, wid = tid >> 5;
    const int wm = wid >> 2, wn = wid & 3;
    const int li = lane & 7, mi = lane >> 3;

    u32 sA[4], sB[4];
    const __half* gA[4];
    const __half* gB[4];
    #pragma unroll
    for (int p = 0; p < 4; ++p) {
        int id = tid + p * 256;
        int row = id >> 3, cc = id & 7;
        u32 sw = (u32)(row * 128 + ((cc ^ (row & 7)) << 4));
        sA[p] = sb + sw;
        gA[p] = A + (size_t)row * 1024 + cc * 8;
        sB[p] = sb + 16384 + sw;
        gB[p] = Bm + (size_t)row * 1024 + cc * 8;
    }
    auto loadA = [&](int s) {
        u32 off = (u32)((s % 3) * GSTG);
        int k0 = s << 6;
        #pragma unroll
        for (int p = 0; p < 4; ++p) CP16(sA[p] + off, gA[p] + k0);
    };
    auto loadB = [&](int s) {
        u32 off = (u32)((s % 3) * GSTG);
        int k0 = s << 6;
        #pragma unroll
        for (int p = 0; p < 4; ++p) CP16(sB[p] + off, gB[p] + k0);
    };
    loadA(0); loadB(0); CPC;
    loadA(1); loadB(1); CPC;

    const u32 bfrag = (u32)(16384 + wn * 4096 + li * 128 + ((mi ^ li) << 4));
    const u32 aRow0 = (u32)((wm * 64 + ((mi & 1) << 3) + li) * 128);

    for (int ch = 0; ch < 16; ++ch) {
        CPW(1);
        __syncthreads();
        u32 st = sb + (u32)((ch % 3) * GSTG);

        #pragma unroll
        for (int half = 0; half < 2; ++half) {
            u32 hx = (u32)(half << 6);
            u32 bb[4][4];
            #pragma unroll
            for (int nt = 0; nt < 4; ++nt)
                LDSM4(bb[nt][0], bb[nt][1], bb[nt][2], bb[nt][3],
                      (st + bfrag + nt * 1024) ^ hx);

            if (half == 0) {
                if (ch + 2 < 16) loadA(ch + 2);
            } else {
                if (ch + 2 < 16) loadB(ch + 2);
                CPC;
            }

            const int kt0 = half * 2, kt1 = half * 2 + 1;
            const u32 x0 = (u32)(((((kt0 << 1) | (mi >> 1))) ^ li) << 4);
            const u32 x1 = (u32)(((((kt1 << 1) | (mi >> 1))) ^ li) << 4);

            u32 ac0[4], ac1[4], an0[4], an1[4];
            LDSM4(ac0[0], ac0[1], ac0[2], ac0[3], st + aRow0 + x0);
            LDSM4(ac1[0], ac1[1], ac1[2], ac1[3], st + aRow0 + x1);
            #pragma unroll
            for (int mt = 0; mt < 4; ++mt) {
                if (mt < 3) {
                    u32 aadr = st + aRow0 + (mt + 1) * 2048;
                    LDSM4(an0[0], an0[1], an0[2], an0[3], aadr + x0);
                    LDSM4(an1[0], an1[1], an1[2], an1[3], aadr + x1);
                }
                #pragma unroll
                for (int nt = 0; nt < 4; ++nt)
                    MMA_F16(c[mt][nt], ac0[0], ac0[1], ac0[2], ac0[3],
                            bb[nt][0], bb[nt][1]);
                #pragma unroll
                for (int nt = 0; nt < 4; ++nt)
                    MMA_F16(c[mt][nt], ac1[0], ac1[1], ac1[2], ac1[3],
                            bb[nt][2], bb[nt][3]);
                if (mt < 3) {
                    #pragma unroll
                    for (int r = 0; r < 4; ++r) { ac0[r] = an0[r]; ac1[r] = an1[r]; }
                }
            }
        }
    }
}

// ============================================================================
// Prep kernels
// ============================================================================
__global__ __launch_bounds__(256) void k_xh(const float* __restrict__ x)
{
    size_t base = ((size_t)blockIdx.x * 256 + threadIdx.x) * 8;
    float4 v0 = *(const float4*)(x + base);
    float4 v1 = *(const float4*)(x + base + 4);
    __half2 h0 = __floats2half2_rn(v0.x, v0.y);
    __half2 h1 = __floats2half2_rn(v0.z, v0.w);
    __half2 h2 = __floats2half2_rn(v1.x, v1.y);
    __half2 h3 = __floats2half2_rn(v1.z, v1.w);
    *(uint4*)(g_xh + base) = make_uint4(*(u32*)&h0, *(u32*)&h1, *(u32*)&h2, *(u32*)&h3);
}

__global__ __launch_bounds__(256) void k_wqh(const float* __restrict__ w)
{
    __shared__ float tile[32][33];
    int bx = blockIdx.x * 32, by = blockIdx.y * 32;
    int tx = threadIdx.x, ty = threadIdx.y;
    float sc = (bx < 1024) ? SCALE_ * LOG2E_ : 1.0f;
    #pragma unroll
    for (int i = 0; i < 32; i += 8)
        tile[ty + i][tx] = w[(size_t)(by + ty + i) * 3072 + bx + tx];
    __syncthreads();
    #pragma unroll
    for (int i = 0; i < 32; i += 8)
        g_wqh[(size_t)(bx + ty + i) * 1024 + by + tx] = __float2half(tile[tx][ty + i] * sc);
}

__global__ __launch_bounds__(256) void k_woutT(const float* __restrict__ w)
{
    __shared__ float tile[32][33];
    int bx = blockIdx.x * 32, by = blockIdx.y * 32;
    int tx = threadIdx.x, ty = threadIdx.y;
    #pragma unroll
    for (int i = 0; i < 32; i += 8)
        tile[ty + i][tx] = w[(size_t)(by + ty + i) * D_ + bx + tx];
    __syncthreads();
    #pragma unroll
    for (int i = 0; i < 32; i += 8)
        g_woutTh[(size_t)(bx + ty + i) * D_ + by + tx] = __float2half(tile[tx][ty + i]);
}

// ============================================================================
// Kernel 1: QKV projection (fp16 1x). q/k stored [bh][s][dh]; V written
// transposed directly into g_vTh.
// ============================================================================
__global__ __launch_bounds__(256, 2) void k_qkv(const float* __restrict__ bias)
{
    extern __shared__ __align__(16) char dsm[];
    u32 sb = smem_u32(dsm);
    const int row0 = blockIdx.y * 128, col0 = blockIdx.x * 128;

    float c[4][4][4]; ZERO_C3(c, 4);
    gemm16_1024(g_xh + (size_t)row0 * 1024, g_wqh + (size_t)col0 * 1024, dsm, sb, c);

    const int lane = threadIdx.x & 31, wid = threadIdx.x >> 5;
    const int wm = wid >> 2, wn = wid & 3, g = lane >> 2, t = lane & 3;
    const int three = col0 >> 10;
    const float bsc = (three == 0) ? SCALE_ * LOG2E_ : 1.0f;
    #pragma unroll
    for (int nt = 0; nt < 4; ++nt) {
        int gcol = col0 + wn * 32 + nt * 8 + t * 2;
        float b0 = __ldg(bias + gcol) * bsc, b1 = __ldg(bias + gcol + 1) * bsc;
        int h = (gcol >> 6) & 15, dh = gcol & 63;
        #pragma unroll
        for (int mt = 0; mt < 4; ++mt)
            #pragma unroll
            for (int hh = 0; hh < 2; ++hh) {
                int gm = row0 + wm * 64 + mt * 16 + hh * 8 + g;
                int b = gm >> 11, s = gm & 2047;
                float v0 = c[mt][nt][hh * 2] + b0, v1 = c[mt][nt][hh * 2 + 1] + b1;
                if (three == 2) {
                    size_t vb = ((size_t)(b * 16 + h) * 64 + dh) * S_ + s;
                    g_vTh[vb]      = __float2half(v0);
                    g_vTh[vb + S_] = __float2half(v1);
                } else {
                    __half* dst = (three == 0) ? g_qh : g_kh;
                    size_t base = ((size_t)(b * 16 + h) * S_ + s) * 64 + dh;
                    __half2 hv = __floats2half2_rn(v0, v1);
                    *(u32*)(dst + base) = *(u32*)&hv;
                }
            }
    }
}

// ============================================================================
// Kernel 2: fused flash attention. NEW: loadKV split — K cp.asyncs issue
// after the QK mma block, V cp.asyncs + commit after exp/rowsum, riding in
// the tensor-pipe shadow instead of colliding with LDSM bursts.
// ============================================================================
#define ATQ   16384
#define ATSTG 16384
__global__ __launch_bounds__(256, 2) void k_attn()
{
    extern __shared__ __align__(16) char dsm[];
    u32 sb = smem_u32(dsm);
    const int tid = threadIdx.x, lane = tid & 31, wid = tid >> 5;
    const int g = lane >> 2, t = lane & 3;
    const int li = lane & 7, mi = lane >> 3;
    const int bh = blockIdx.y, row0 = blockIdx.x * 128;

    // Q producer (group 0)
    {
        const __half* qg = g_qh + ((size_t)bh * S_ + row0) * 64;
        #pragma unroll
        for (int p = 0; p < 4; ++p) {
            int id = tid + p * 256;
            int row = id >> 3, cc = id & 7;
            u32 off = (u32)(row * 128 + ((cc ^ (row & 7)) << 4));
            CP16(sb + off, qg + (size_t)row * 64 + cc * 8);
        }
        CPC;
    }

    // KV producers
    u32 kOff[2], vOff[2];
    const __half* kG[2];
    const __half* vG[2];
    #pragma unroll
    for (int p = 0; p < 2; ++p) {
        int id = tid + p * 256;
        int row = id >> 3, cc = id & 7;
        u32 sw = (u32)(row * 128 + ((cc ^ (row & 7)) << 4));
        kOff[p] = sw;
        kG[p] = g_kh + ((size_t)bh * S_ + row) * 64 + cc * 8;
        vOff[p] = 8192 + sw;
        vG[p] = g_vTh + ((size_t)bh * 64 + row) * S_ + cc * 8;
    }
    auto loadK = [&](int it) {
        u32 so = sb + ATQ + (u32)((it & 3) * ATSTG);
        int kv0 = it * 64;
        #pragma unroll
        for (int p = 0; p < 2; ++p) CP16(so + kOff[p], kG[p] + (size_t)kv0 * 64);
    };
    auto loadV = [&](int it) {
        u32 so = sb + ATQ + (u32)((it & 3) * ATSTG);
        int kv0 = it * 64;
        #pragma unroll
        for (int p = 0; p < 2; ++p) CP16(so + vOff[p], vG[p] + kv0);
    };
    loadK(0); loadV(0); CPC;
    loadK(1); loadV(1); CPC;
    loadK(2); loadV(2); CPC;

    // Q fragments -> registers
    CPW(3);
    __syncthreads();
    u32 qf[4][4];
    {
        u32 qBase = sb + (u32)((wid * 16 + ((mi & 1) << 3) + li) * 128);
        #pragma unroll
        for (int kt = 0; kt < 4; ++kt) {
            u32 x = (u32)(((((kt << 1) | (mi >> 1))) ^ li) << 4);
            LDSM4(qf[kt][0], qf[kt][1], qf[kt][2], qf[kt][3], qBase + x);
        }
    }

    const u32 fragBase = (u32)(li * 128 + ((mi ^ li) << 4));
    const u32 ONE2 = 0x3C003C00u;   // half2(1, 1)

    float co[8][4]; ZERO_C2(co, 8);
    float cls[4];
    #pragma unroll
    for (int r = 0; r < 4; ++r) cls[r] = 0.f;

    for (int it = 0; it < 32; ++it) {
        CPW(2);
        __syncthreads();
        u32 stK = sb + ATQ + (u32)((it & 3) * ATSTG);
        u32 stV = stK + 8192;
        const bool pf = (it + 3 < 32);

        // S(log2) = Q K^T
        float cs[8][4]; ZERO_C2(cs, 8);
        #pragma unroll
        for (int nt = 0; nt < 8; ++nt) {
            u32 k0, k1, k2, k3, k4, k5, k6, k7;
            u32 adr = stK + fragBase + nt * 1024;
            LDSM4(k0, k1, k2, k3, adr);
            LDSM4(k4, k5, k6, k7, adr ^ 64);
            MMA_F16(cs[nt], qf[0][0], qf[0][1], qf[0][2], qf[0][3], k0, k1);
            MMA_F16(cs[nt], qf[1][0], qf[1][1], qf[1][2], qf[1][3], k2, k3);
            MMA_F16(cs[nt], qf[2][0], qf[2][1], qf[2][2], qf[2][3], k4, k5);
            MMA_F16(cs[nt], qf[3][0], qf[3][1], qf[3][2], qf[3][3], k6, k7);
        }

        // next-stage K loads ride the QK mma shadow
        if (pf) loadK(it + 3);

        // P = 2^S in fp16x2; pack into PV A-fragments
        u32 ap[4][4];
        #pragma unroll
        for (int nt = 0; nt < 8; ++nt) {
            u32 p01, p23;
            EXP2_PACK(p01, cs[nt][0], cs[nt][1]);
            EXP2_PACK(p23, cs[nt][2], cs[nt][3]);
            ap[nt >> 1][(nt & 1) * 2 + 0] = p01;
            ap[nt >> 1][(nt & 1) * 2 + 1] = p23;
        }

        // row sums (exact fp32)
        #pragma unroll
        for (int kt = 0; kt < 4; ++kt)
            MMA_F16(cls, ap[kt][0], ap[kt][1], ap[kt][2], ap[kt][3], ONE2, ONE2);

        // next-stage V loads + commit ride the exp/rowsum shadow
        if (pf) loadV(it + 3);
        CPC;

        // O += P V
        #pragma unroll
        for (int nt = 0; nt < 8; ++nt) {
            u32 v0, v1, v2, v3, v4, v5, v6, v7;
            u32 adr = stV + fragBase + nt * 1024;
            LDSM4(v0, v1, v2, v3, adr);
            LDSM4(v4, v5, v6, v7, adr ^ 64);
            MMA_F16(co[nt], ap[0][0], ap[0][1], ap[0][2], ap[0][3], v0, v1);
            MMA_F16(co[nt], ap[1][0], ap[1][1], ap[1][2], ap[1][3], v2, v3);
            MMA_F16(co[nt], ap[2][0], ap[2][1], ap[2][2], ap[2][3], v4, v5);
            MMA_F16(co[nt], ap[3][0], ap[3][1], ap[3][2], ap[3][3], v6, v7);
        }
    }

    // normalize and write (cls[0]/cls[2] hold this thread's row sums)
    float inv0 = 1.0f / cls[0], inv1 = 1.0f / cls[2];

    const int b = bh >> 4, h = bh & 15;
    int r0 = row0 + wid * 16 + g;
    __half* o0 = g_aoh + ((size_t)b * S_ + r0) * D_ + h * 64;
    __half* o1 = o0 + (size_t)8 * D_;
    #pragma unroll
    for (int nt = 0; nt < 8; ++nt) {
        int dh = nt * 8 + t * 2;
        __half2 w0 = __floats2half2_rn(co[nt][0] * inv0, co[nt][1] * inv0);
        __half2 w1 = __floats2half2_rn(co[nt][2] * inv1, co[nt][3] * inv1);
        *(u32*)(o0 + dh) = *(u32*)&w0;
        *(u32*)(o1 + dh) = *(u32*)&w1;
    }
}

// ============================================================================
// Kernel 3: output projection (fp16 1x)
// ============================================================================
__global__ __launch_bounds__(256, 2) void k_out(
    const float* __restrict__ bias, float* __restrict__ out)
{
    extern __shared__ __align__(16) char dsm[];
    u32 sb = smem_u32(dsm);
    const int row0 = blockIdx.y * 128, col0 = blockIdx.x * 128;

    float c[4][4][4]; ZERO_C3(c, 4);
    gemm16_1024(g_aoh + (size_t)row0 * D_, g_woutTh + (size_t)col0 * D_, dsm, sb, c);

    const int lane = threadIdx.x & 31, wid = threadIdx.x >> 5;
    const int wm = wid >> 2, wn = wid & 3, g = lane >> 2, t = lane & 3;
    #pragma unroll
    for (int nt = 0; nt < 4; ++nt) {
        int gcol = col0 + wn * 32 + nt * 8 + t * 2;
        float b0 = __ldg(bias + gcol), b1 = __ldg(bias + gcol + 1);
        #pragma unroll
        for (int mt = 0; mt < 4; ++mt)
            #pragma unroll
            for (int hh = 0; hh < 2; ++hh) {
                int gm = row0 + wm * 64 + mt * 16 + hh * 8 + g;
                *(float2*)(out + (size_t)gm * D_ + gcol) =
                    make_float2(c[mt][nt][hh * 2] + b0, c[mt][nt][hh * 2 + 1] + b1);
            }
    }
}

// ---------------------------------------------------------------------------
#define DYN_G16 (3 * GSTG)          // 98304
#define DYN_ATT (ATQ + 4 * ATSTG)   // 81920

extern "C" void kernel_launch(void* const* d_in, const int* in_sizes, int n_in,
                              void* d_out, int out_size)
{
    (void)in_sizes; (void)n_in; (void)out_size;
    const float* x     = (const float*)d_in[0];
    const float* w_qkv = (const float*)d_in[1];
    const float* b_qkv = (const float*)d_in[2];
    const float* w_out = (const float*)d_in[3];
    const float* b_out = (const float*)d_in[4];
    float* out = (float*)d_out;

    cudaFuncSetAttribute(k_qkv,  cudaFuncAttributeMaxDynamicSharedMemorySize, DYN_G16);
    cudaFuncSetAttribute(k_attn, cudaFuncAttributeMaxDynamicSharedMemorySize, DYN_ATT);
    cudaFuncSetAttribute(k_out,  cudaFuncAttributeMaxDynamicSharedMemorySize, DYN_G16);

    k_xh<<<4096, 256>>>(x);
    k_wqh<<<dim3(96, 32), dim3(32, 8)>>>(w_qkv);
    k_woutT<<<dim3(32, 32), dim3(32, 8)>>>(w_out);

    k_qkv<<<dim3(24, 64), 256, DYN_G16>>>(b_qkv);
    k_attn<<<dim3(16, 64), 256, DYN_ATT>>>();
    k_out<<<dim3(8, 64), 256, DYN_G16>>>(b_out, out);
}